// round 2
// baseline (speedup 1.0000x reference)
#include <cuda_runtime.h>
#include <cuda_bf16.h>

// Problem constants
#define TT   12
#define NN   10000
#define FIN  64
#define NH   4
#define CC   32
#define HC   128      // NH*CC
#define TNN  120000   // TT*NN
#define EE   1000000
#define SL0  110000   // first node of time-slice t=11
#define HID  32

// ---------------- scratch (device globals; no allocation allowed) ----------
__device__ float    g_h[TNN * HC];          // GAT node features
__device__ float    g_asrc[TNN * 4];
__device__ float    g_adst[TNN * 4];
__device__ unsigned g_mkey[NN * 4];         // ordered-int max keys
__device__ float    g_denom[NN * 4];
__device__ float4   g_acc[NN * (HC / 4)];   // message accumulator (slice dsts only)
__device__ float4   g_pre2[(NN + 2) * HID]; // LSTM gate pre-act, packed {i,f,g,o} per unit (+2 pad rows)
__device__ float    g_hist[NN * HID];       // h state after each step
__device__ float    g_easum;
__device__ float    g_kvec[4];

// ---------------- helpers ---------------------------------------------------
__device__ __forceinline__ unsigned fkey(float f) {
    unsigned u = __float_as_uint(f);
    return (u & 0x80000000u) ? ~u : (u | 0x80000000u);
}
__device__ __forceinline__ float unfkey(unsigned k) {
    return (k & 0x80000000u) ? __uint_as_float(k & 0x7fffffffu) : __uint_as_float(~k);
}
__device__ __forceinline__ float lrelu(float x) { return fmaxf(x, 0.f) + 0.2f * fminf(x, 0.f); }
__device__ __forceinline__ float sigf(float x) { return __fdividef(1.f, 1.f + __expf(-x)); }
__device__ __forceinline__ float tnf (float x) { return __fdividef(2.f, 1.f + __expf(-2.f * x)) - 1.f; }

// packed f32x2 helpers (sm_100-family; ptxas never emits these from C++)
typedef unsigned long long u64;
__device__ __forceinline__ u64 fma2(u64 a, u64 b, u64 c) {
    u64 d; asm("fma.rn.f32x2 %0, %1, %2, %3;" : "=l"(d) : "l"(a), "l"(b), "l"(c)); return d;
}
__device__ __forceinline__ u64 add2(u64 a, u64 b) {
    u64 d; asm("add.rn.f32x2 %0, %1, %2;" : "=l"(d) : "l"(a), "l"(b)); return d;
}
__device__ __forceinline__ u64 pk2(float lo, float hi) {
    u64 d; asm("mov.b64 %0, {%1, %2};" : "=l"(d) : "f"(lo), "f"(hi)); return d;
}
__device__ __forceinline__ void up2(u64 v, float& lo, float& hi) {
    asm("mov.b64 {%0, %1}, %2;" : "=f"(lo), "=f"(hi) : "l"(v));
}

// ---------------- k_init: zero accumulators, compute k[h] -------------------
__global__ void k_init(const float* __restrict__ W_edge, const float* __restrict__ att_edge) {
    int idx = blockIdx.x * blockDim.x + threadIdx.x;
    if (idx < NN * HC) ((float*)g_acc)[idx] = 0.f;
    if (idx < NN * 4) { g_denom[idx] = 0.f; g_mkey[idx] = 0u; }
    if (idx >= NN * HC && idx < NN * HC + 2 * HID * 4) {
        ((float*)g_pre2)[NN * HID * 4 + (idx - NN * HC)] = 0.f;  // zero pad rows
    }
    if (idx == 0) g_easum = 0.f;
    if (idx < 4) {
        float s = 0.f;
        #pragma unroll
        for (int c = 0; c < CC; c++) s += W_edge[idx * CC + c] * att_edge[idx * CC + c];
        g_kvec[idx] = s;
    }
}

// ---------------- k_easum: mean of edge_attr --------------------------------
__global__ void k_easum(const float* __restrict__ ea) {
    int idx = blockIdx.x * blockDim.x + threadIdx.x;
    int stride = gridDim.x * blockDim.x;
    float v = 0.f;
    for (int i = idx; i < EE; i += stride) v += ea[i];
    #pragma unroll
    for (int o = 16; o; o >>= 1) v += __shfl_down_sync(0xffffffffu, v, o);
    __shared__ float sm[8];
    if ((threadIdx.x & 31) == 0) sm[threadIdx.x >> 5] = v;
    __syncthreads();
    if (threadIdx.x < 8) {
        v = sm[threadIdx.x];
        #pragma unroll
        for (int o = 4; o; o >>= 1) v += __shfl_down_sync(0xffu, v, o);
        if (threadIdx.x == 0) atomicAdd(&g_easum, v);
    }
}

// ---------------- k_feat: h = x @ W_gat ; a_src/a_dst ----------------------
__global__ void k_feat(const float* __restrict__ x, const float* __restrict__ W_gat,
                       const float* __restrict__ att_src, const float* __restrict__ att_dst) {
    __shared__ float sW[FIN * HC];     // 32 KB
    __shared__ float sAs[HC], sAd[HC];
    for (int i = threadIdx.x; i < FIN * HC; i += blockDim.x) sW[i] = W_gat[i];
    if (threadIdx.x < HC) { sAs[threadIdx.x] = att_src[threadIdx.x]; sAd[threadIdx.x] = att_dst[threadIdx.x]; }
    __syncthreads();

    int warp = threadIdx.x >> 5, lane = threadIdx.x & 31;
    int nw = blockDim.x >> 5;
    const float4* sW4 = (const float4*)sW;

    for (int r = blockIdx.x * nw + warp; r < TNN; r += gridDim.x * nw) {
        float x0 = x[r * FIN + lane];
        float x1 = x[r * FIN + 32 + lane];
        float4 acc = make_float4(0.f, 0.f, 0.f, 0.f);
        #pragma unroll
        for (int k = 0; k < FIN; k++) {
            float xk = __shfl_sync(0xffffffffu, (k < 32) ? x0 : x1, k & 31);
            float4 w = sW4[k * 32 + lane];
            acc.x = fmaf(xk, w.x, acc.x); acc.y = fmaf(xk, w.y, acc.y);
            acc.z = fmaf(xk, w.z, acc.z); acc.w = fmaf(xk, w.w, acc.w);
        }
        ((float4*)g_h)[r * 32 + lane] = acc;

        int base = lane * 4;   // == head*32 + c  (head = lane>>3)
        float ps = acc.x * sAs[base] + acc.y * sAs[base + 1] + acc.z * sAs[base + 2] + acc.w * sAs[base + 3];
        float pd = acc.x * sAd[base] + acc.y * sAd[base + 1] + acc.z * sAd[base + 2] + acc.w * sAd[base + 3];
        #pragma unroll
        for (int o = 4; o; o >>= 1) {
            ps += __shfl_down_sync(0xffffffffu, ps, o);
            pd += __shfl_down_sync(0xffffffffu, pd, o);
        }
        if ((lane & 7) == 0) {
            g_asrc[r * 4 + (lane >> 3)] = ps;
            g_adst[r * 4 + (lane >> 3)] = pd;
        }
    }
}

// ---------------- edge passes (only dst in slice t=11) ----------------------
__device__ __forceinline__ bool edge_fetch(int e, const int* __restrict__ ei,
                                           const float* __restrict__ ea,
                                           int& src, int& dst, float& a) {
    if (e < EE) {
        dst = ei[EE + e];
        if (dst < SL0) return false;
        src = ei[e];
        a = ea[e];
    } else {                       // self-loop for slice node
        dst = SL0 + (e - EE);
        src = dst;
        a = g_easum * (1.f / (float)EE);
    }
    return true;
}

__global__ void k_pass1(const int* __restrict__ ei, const float* __restrict__ ea) {
    int e = blockIdx.x * blockDim.x + threadIdx.x;
    if (e >= EE + NN) return;
    int src, dst; float a;
    if (!edge_fetch(e, ei, ea, src, dst, a)) return;
    int d = dst - SL0;
    float4 as = *(const float4*)&g_asrc[src * 4];
    float4 ad = *(const float4*)&g_adst[dst * 4];
    atomicMax(&g_mkey[d * 4 + 0], fkey(lrelu(as.x + ad.x + a * g_kvec[0])));
    atomicMax(&g_mkey[d * 4 + 1], fkey(lrelu(as.y + ad.y + a * g_kvec[1])));
    atomicMax(&g_mkey[d * 4 + 2], fkey(lrelu(as.z + ad.z + a * g_kvec[2])));
    atomicMax(&g_mkey[d * 4 + 3], fkey(lrelu(as.w + ad.w + a * g_kvec[3])));
}

__global__ void k_pass2(const int* __restrict__ ei, const float* __restrict__ ea) {
    int e = blockIdx.x * blockDim.x + threadIdx.x;
    if (e >= EE + NN) return;
    int src, dst; float a;
    if (!edge_fetch(e, ei, ea, src, dst, a)) return;
    int d = dst - SL0;
    float4 as = *(const float4*)&g_asrc[src * 4];
    float4 ad = *(const float4*)&g_adst[dst * 4];
    float ex[4];
    ex[0] = __expf(lrelu(as.x + ad.x + a * g_kvec[0]) - unfkey(g_mkey[d * 4 + 0]));
    ex[1] = __expf(lrelu(as.y + ad.y + a * g_kvec[1]) - unfkey(g_mkey[d * 4 + 1]));
    ex[2] = __expf(lrelu(as.z + ad.z + a * g_kvec[2]) - unfkey(g_mkey[d * 4 + 2]));
    ex[3] = __expf(lrelu(as.w + ad.w + a * g_kvec[3]) - unfkey(g_mkey[d * 4 + 3]));
    atomicAdd(&g_denom[d * 4 + 0], ex[0]);
    atomicAdd(&g_denom[d * 4 + 1], ex[1]);
    atomicAdd(&g_denom[d * 4 + 2], ex[2]);
    atomicAdd(&g_denom[d * 4 + 3], ex[3]);
    const float4* hs = (const float4*)&g_h[src * HC];
    float4* accp = &g_acc[d * 32];
    #pragma unroll
    for (int h = 0; h < 4; h++) {
        float e_h = ex[h];
        #pragma unroll
        for (int q = 0; q < 8; q++) {
            float4 hv = hs[h * 8 + q];
            atomicAdd(&accp[h * 8 + q],
                      make_float4(e_h * hv.x, e_h * hv.y, e_h * hv.z, e_h * hv.w));
        }
    }
}

// ---------------- k_gatpre: finalize GAT row + gate GEMM --------------------
// blockDim = 128. dynamic smem: transposed W_ih (128x128 floats = 64 KB).
// Output layout: g_pre2[d*32 + unit] = {pre_i, pre_f, pre_g, pre_o}
__global__ void k_gatpre(const float* __restrict__ W_ih, const float* __restrict__ b_ih,
                         const float* __restrict__ b_hh, const float* __restrict__ gat_bias) {
    extern __shared__ float sWt[];           // sWt[k*128 + j] = W_ih[j*128 + k]
    __shared__ float srow[HC];
    for (int idx = threadIdx.x; idx < HC * HC; idx += blockDim.x) {
        int j = idx / HC, k = idx % HC;      // coalesced read of W_ih
        sWt[k * HC + j] = W_ih[idx];
    }
    __syncthreads();

    int j = threadIdx.x;                      // 0..127, j = gate*32 + unit
    int gate = j >> 5, unit = j & 31;
    float bj = b_ih[j] + b_hh[j];
    float gbias = gat_bias[j];

    for (int d = blockIdx.x; d < NN; d += gridDim.x) {
        float den = g_denom[d * 4 + (j >> 5)];
        float v = ((const float*)g_acc)[d * HC + j];
        v = __fdividef(v, den + 1e-16f) + gbias;
        srow[j] = fmaxf(v, 0.f);
        __syncthreads();
        float s = bj;
        #pragma unroll 8
        for (int k = 0; k < HC; k++) s = fmaf(srow[k], sWt[k * HC + j], s);
        ((float*)g_pre2)[d * HC + unit * 4 + gate] = s;
        __syncthreads();
    }
}

// ---------------- k_chain: sequential LSTM (chain t=11 only) ----------------
// Single warp, lane j owns hidden unit j. W_hh register-resident, packed f32x2.
// h exchanged via smem as duplicated (h,h) u64 pairs; g_pre2 prefetched 2 deep.
__global__ void __launch_bounds__(32, 1) k_chain(const float* __restrict__ W_hh) {
    int j = threadIdx.x;
    __shared__ u64 shh[2][HID];               // duplicated-pair h buffers

    // packed weights: Wif[k] = (W_i[j][k], W_f[j][k]), Wgo[k] = (W_g[j][k], W_o[j][k])
    u64 Wif[32], Wgo[32];
    #pragma unroll
    for (int k = 0; k < 32; k++) {
        Wif[k] = pk2(W_hh[( 0 + j) * 32 + k], W_hh[(32 + j) * 32 + k]);
        Wgo[k] = pk2(W_hh[(64 + j) * 32 + k], W_hh[(96 + j) * 32 + k]);
    }
    float c = 0.f;
    shh[0][j] = pk2(0.f, 0.f);
    __syncwarp();

    // 2-deep prefetch pipeline on g_pre2 (rows NN, NN+1 are zero pad)
    float4 pc = g_pre2[0 * HID + j];
    float4 pn = g_pre2[1 * HID + j];

    #pragma unroll 1
    for (int n = 0; n < NN; n++) {
        int rb = n & 1;
        float4 pf2 = g_pre2[(n + 2) * HID + j];   // prefetch n+2

        u64 aif0 = pk2(pc.x, pc.y), ago0 = pk2(pc.z, pc.w);
        u64 aif1 = 0ull, ago1 = 0ull;
        const ulonglong2* s2 = (const ulonglong2*)shh[rb];
        #pragma unroll
        for (int q = 0; q < 16; q++) {
            ulonglong2 hv = s2[q];                // pairs for k=2q, 2q+1
            aif0 = fma2(hv.x, Wif[2 * q], aif0);
            ago0 = fma2(hv.x, Wgo[2 * q], ago0);
            aif1 = fma2(hv.y, Wif[2 * q + 1], aif1);
            ago1 = fma2(hv.y, Wgo[2 * q + 1], ago1);
        }
        u64 aif = add2(aif0, aif1);
        u64 ago = add2(ago0, ago1);
        float ai, af, ag, ao;
        up2(aif, ai, af);
        up2(ago, ag, ao);

        float ii = sigf(ai), ff = sigf(af), gg = tnf(ag), oo = sigf(ao);
        c = ff * c + ii * gg;
        float hnew = oo * tnf(c);
        g_hist[n * HID + j] = hnew;
        shh[rb ^ 1][j] = pk2(hnew, hnew);
        __syncwarp();
        pc = pn; pn = pf2;
    }
}

// ---------------- k_out: y = hist @ W_fc + b_fc -----------------------------
__global__ void k_out(const float* __restrict__ W_fc, const float* __restrict__ b_fc,
                      float* __restrict__ out) {
    int gw = (blockIdx.x * blockDim.x + threadIdx.x) >> 5;
    int lane = threadIdx.x & 31;
    if (gw >= NN) return;
    float v = g_hist[gw * HID + lane] * W_fc[lane];
    #pragma unroll
    for (int o = 16; o; o >>= 1) v += __shfl_down_sync(0xffffffffu, v, o);
    if (lane == 0) out[gw] = v + b_fc[0];
}

// ---------------- launch -----------------------------------------------------
extern "C" void kernel_launch(void* const* d_in, const int* in_sizes, int n_in,
                              void* d_out, int out_size) {
    const float* x_seq     = (const float*)d_in[0];
    const int*   edge_index= (const int*  )d_in[1];
    const float* edge_attr = (const float*)d_in[2];
    const float* W_gat     = (const float*)d_in[3];
    const float* att_src   = (const float*)d_in[4];
    const float* att_dst   = (const float*)d_in[5];
    const float* att_edge  = (const float*)d_in[6];
    const float* W_edge    = (const float*)d_in[7];
    const float* gat_bias  = (const float*)d_in[8];
    const float* W_ih      = (const float*)d_in[9];
    const float* W_hh      = (const float*)d_in[10];
    const float* b_ih      = (const float*)d_in[11];
    const float* b_hh      = (const float*)d_in[12];
    const float* W_fc      = (const float*)d_in[13];
    const float* b_fc      = (const float*)d_in[14];
    float* out = (float*)d_out;

    (void)in_sizes; (void)n_in; (void)out_size;

    cudaFuncSetAttribute(k_gatpre, cudaFuncAttributeMaxDynamicSharedMemorySize, HC * HC * 4);

    k_init<<<(NN * HC + 2 * HID * 4 + 255) / 256, 256>>>(W_edge, att_edge);
    k_easum<<<296, 256>>>(edge_attr);
    k_feat<<<592, 256>>>(x_seq, W_gat, att_src, att_dst);
    int eblocks = (EE + NN + 255) / 256;
    k_pass1<<<eblocks, 256>>>(edge_index, edge_attr);
    k_pass2<<<eblocks, 256>>>(edge_index, edge_attr);
    k_gatpre<<<440, 128, HC * HC * 4>>>(W_ih, b_ih, b_hh, gat_bias);
    k_chain<<<1, 32>>>(W_hh);
    k_out<<<(NN * 32 + 255) / 256, 256>>>(W_fc, b_fc, out);
}

// round 3
// speedup vs baseline: 1.2187x; 1.2187x over previous
#include <cuda_runtime.h>
#include <cuda_bf16.h>

// Problem constants
#define TT   12
#define NN   10000
#define FIN  64
#define NH   4
#define CC   32
#define HC   128      // NH*CC
#define TNN  120000   // TT*NN
#define EE   1000000
#define SL0  110000   // first node of time-slice t=11
#define HID  32

// ---------------- scratch (device globals; no allocation allowed) ----------
__device__ float    g_h[TNN * HC];          // GAT node features
__device__ float    g_asrc[TNN * 4];
__device__ float    g_adst[TNN * 4];
__device__ unsigned g_mkey[NN * 4];         // ordered-int max keys
__device__ float    g_denom[NN * 4];
__device__ float4   g_acc[NN * (HC / 4)];   // message accumulator (slice dsts only)
__device__ float    g_pre[(NN + 2) * HC];   // LSTM gate pre-activations (+2 pad rows)
__device__ float    g_hist[NN * HID];       // h state after each step
__device__ float    g_easum;
__device__ float    g_kvec[4];

// ---------------- helpers ---------------------------------------------------
__device__ __forceinline__ unsigned fkey(float f) {
    unsigned u = __float_as_uint(f);
    return (u & 0x80000000u) ? ~u : (u | 0x80000000u);
}
__device__ __forceinline__ float unfkey(unsigned k) {
    return (k & 0x80000000u) ? __uint_as_float(k & 0x7fffffffu) : __uint_as_float(~k);
}
__device__ __forceinline__ float lrelu(float x) { return fmaxf(x, 0.f) + 0.2f * fminf(x, 0.f); }
__device__ __forceinline__ float sigf(float x) { return __fdividef(1.f, 1.f + __expf(-x)); }
__device__ __forceinline__ float tnf (float x) { return __fdividef(2.f, 1.f + __expf(-2.f * x)) - 1.f; }

// ---------------- k_init: zero accumulators, compute k[h] -------------------
__global__ void k_init(const float* __restrict__ W_edge, const float* __restrict__ att_edge) {
    int idx = blockIdx.x * blockDim.x + threadIdx.x;
    if (idx < NN * HC) ((float*)g_acc)[idx] = 0.f;
    if (idx < NN * 4) { g_denom[idx] = 0.f; g_mkey[idx] = 0u; }
    if (idx < 2 * HC) g_pre[NN * HC + idx] = 0.f;   // zero pad rows
    if (idx == 0) g_easum = 0.f;
    if (idx < 4) {
        float s = 0.f;
        #pragma unroll
        for (int c = 0; c < CC; c++) s += W_edge[idx * CC + c] * att_edge[idx * CC + c];
        g_kvec[idx] = s;
    }
}

// ---------------- k_easum: mean of edge_attr --------------------------------
__global__ void k_easum(const float* __restrict__ ea) {
    int idx = blockIdx.x * blockDim.x + threadIdx.x;
    int stride = gridDim.x * blockDim.x;
    float v = 0.f;
    for (int i = idx; i < EE; i += stride) v += ea[i];
    #pragma unroll
    for (int o = 16; o; o >>= 1) v += __shfl_down_sync(0xffffffffu, v, o);
    __shared__ float sm[8];
    if ((threadIdx.x & 31) == 0) sm[threadIdx.x >> 5] = v;
    __syncthreads();
    if (threadIdx.x < 8) {
        v = sm[threadIdx.x];
        #pragma unroll
        for (int o = 4; o; o >>= 1) v += __shfl_down_sync(0xffu, v, o);
        if (threadIdx.x == 0) atomicAdd(&g_easum, v);
    }
}

// ---------------- k_feat: h = x @ W_gat ; a_src/a_dst ----------------------
__global__ void k_feat(const float* __restrict__ x, const float* __restrict__ W_gat,
                       const float* __restrict__ att_src, const float* __restrict__ att_dst) {
    __shared__ float sW[FIN * HC];     // 32 KB
    __shared__ float sAs[HC], sAd[HC];
    for (int i = threadIdx.x; i < FIN * HC; i += blockDim.x) sW[i] = W_gat[i];
    if (threadIdx.x < HC) { sAs[threadIdx.x] = att_src[threadIdx.x]; sAd[threadIdx.x] = att_dst[threadIdx.x]; }
    __syncthreads();

    int warp = threadIdx.x >> 5, lane = threadIdx.x & 31;
    int nw = blockDim.x >> 5;
    const float4* sW4 = (const float4*)sW;

    for (int r = blockIdx.x * nw + warp; r < TNN; r += gridDim.x * nw) {
        float x0 = x[r * FIN + lane];
        float x1 = x[r * FIN + 32 + lane];
        float4 acc = make_float4(0.f, 0.f, 0.f, 0.f);
        #pragma unroll
        for (int k = 0; k < FIN; k++) {
            float xk = __shfl_sync(0xffffffffu, (k < 32) ? x0 : x1, k & 31);
            float4 w = sW4[k * 32 + lane];
            acc.x = fmaf(xk, w.x, acc.x); acc.y = fmaf(xk, w.y, acc.y);
            acc.z = fmaf(xk, w.z, acc.z); acc.w = fmaf(xk, w.w, acc.w);
        }
        ((float4*)g_h)[r * 32 + lane] = acc;

        int base = lane * 4;   // == head*32 + c  (head = lane>>3)
        float ps = acc.x * sAs[base] + acc.y * sAs[base + 1] + acc.z * sAs[base + 2] + acc.w * sAs[base + 3];
        float pd = acc.x * sAd[base] + acc.y * sAd[base + 1] + acc.z * sAd[base + 2] + acc.w * sAd[base + 3];
        #pragma unroll
        for (int o = 4; o; o >>= 1) {
            ps += __shfl_down_sync(0xffffffffu, ps, o);
            pd += __shfl_down_sync(0xffffffffu, pd, o);
        }
        if ((lane & 7) == 0) {
            g_asrc[r * 4 + (lane >> 3)] = ps;
            g_adst[r * 4 + (lane >> 3)] = pd;
        }
    }
}

// ---------------- edge passes (only dst in slice t=11) ----------------------
__device__ __forceinline__ bool edge_fetch(int e, const int* __restrict__ ei,
                                           const float* __restrict__ ea,
                                           int& src, int& dst, float& a) {
    if (e < EE) {
        dst = ei[EE + e];
        if (dst < SL0) return false;
        src = ei[e];
        a = ea[e];
    } else {                       // self-loop for slice node
        dst = SL0 + (e - EE);
        src = dst;
        a = g_easum * (1.f / (float)EE);
    }
    return true;
}

__global__ void k_pass1(const int* __restrict__ ei, const float* __restrict__ ea) {
    int e = blockIdx.x * blockDim.x + threadIdx.x;
    if (e >= EE + NN) return;
    int src, dst; float a;
    if (!edge_fetch(e, ei, ea, src, dst, a)) return;
    int d = dst - SL0;
    float4 as = *(const float4*)&g_asrc[src * 4];
    float4 ad = *(const float4*)&g_adst[dst * 4];
    atomicMax(&g_mkey[d * 4 + 0], fkey(lrelu(as.x + ad.x + a * g_kvec[0])));
    atomicMax(&g_mkey[d * 4 + 1], fkey(lrelu(as.y + ad.y + a * g_kvec[1])));
    atomicMax(&g_mkey[d * 4 + 2], fkey(lrelu(as.z + ad.z + a * g_kvec[2])));
    atomicMax(&g_mkey[d * 4 + 3], fkey(lrelu(as.w + ad.w + a * g_kvec[3])));
}

__global__ void k_pass2(const int* __restrict__ ei, const float* __restrict__ ea) {
    int e = blockIdx.x * blockDim.x + threadIdx.x;
    if (e >= EE + NN) return;
    int src, dst; float a;
    if (!edge_fetch(e, ei, ea, src, dst, a)) return;
    int d = dst - SL0;
    float4 as = *(const float4*)&g_asrc[src * 4];
    float4 ad = *(const float4*)&g_adst[dst * 4];
    float ex[4];
    ex[0] = __expf(lrelu(as.x + ad.x + a * g_kvec[0]) - unfkey(g_mkey[d * 4 + 0]));
    ex[1] = __expf(lrelu(as.y + ad.y + a * g_kvec[1]) - unfkey(g_mkey[d * 4 + 1]));
    ex[2] = __expf(lrelu(as.z + ad.z + a * g_kvec[2]) - unfkey(g_mkey[d * 4 + 2]));
    ex[3] = __expf(lrelu(as.w + ad.w + a * g_kvec[3]) - unfkey(g_mkey[d * 4 + 3]));
    atomicAdd(&g_denom[d * 4 + 0], ex[0]);
    atomicAdd(&g_denom[d * 4 + 1], ex[1]);
    atomicAdd(&g_denom[d * 4 + 2], ex[2]);
    atomicAdd(&g_denom[d * 4 + 3], ex[3]);
    const float4* hs = (const float4*)&g_h[src * HC];
    float4* accp = &g_acc[d * 32];
    #pragma unroll
    for (int h = 0; h < 4; h++) {
        float e_h = ex[h];
        #pragma unroll
        for (int q = 0; q < 8; q++) {
            float4 hv = hs[h * 8 + q];
            atomicAdd(&accp[h * 8 + q],
                      make_float4(e_h * hv.x, e_h * hv.y, e_h * hv.z, e_h * hv.w));
        }
    }
}

// ---------------- k_gatpre: finalize GAT row + gate GEMM --------------------
// blockDim = 128. dynamic smem: transposed W_ih (128x128 floats = 64 KB).
__global__ void k_gatpre(const float* __restrict__ W_ih, const float* __restrict__ b_ih,
                         const float* __restrict__ b_hh, const float* __restrict__ gat_bias) {
    extern __shared__ float sWt[];           // sWt[k*128 + j] = W_ih[j*128 + k]
    __shared__ float srow[HC];
    for (int idx = threadIdx.x; idx < HC * HC; idx += blockDim.x) {
        int j = idx / HC, k = idx % HC;      // coalesced read of W_ih
        sWt[k * HC + j] = W_ih[idx];
    }
    __syncthreads();

    int j = threadIdx.x;                      // 0..127
    float bj = b_ih[j] + b_hh[j];
    float gbias = gat_bias[j];

    for (int d = blockIdx.x; d < NN; d += gridDim.x) {
        float den = g_denom[d * 4 + (j >> 5)];
        float v = ((const float*)g_acc)[d * HC + j];
        v = __fdividef(v, den + 1e-16f) + gbias;
        srow[j] = fmaxf(v, 0.f);
        __syncthreads();
        float s = bj;
        #pragma unroll 8
        for (int k = 0; k < HC; k++) s = fmaf(srow[k], sWt[k * HC + j], s);
        g_pre[d * HC + j] = s;
        __syncthreads();
    }
}

// ---------------- k_chain4: sequential LSTM, 4 warps = 4 SMSPs ---------------
// Warp g computes gate g (i/f/g/o) for all 32 units; lane = hidden unit.
// act double-buffered by parity -> ONE __syncthreads per step.
// Each warp keeps a private smem copy of h and redundantly computes c/h.
__global__ void __launch_bounds__(128, 1) k_chain4(const float* __restrict__ W_hh) {
    int lane = threadIdx.x & 31;
    int g    = threadIdx.x >> 5;                  // gate index 0..3 (i,f,g,o)
    __shared__ float s_act[2][4][HID];            // [parity][gate][unit]
    __shared__ float s_h[4][HID];                 // per-warp private h copy

    // weights: row (g*32+lane) of W_hh, 32 floats in registers
    float W[32];
    #pragma unroll
    for (int k = 0; k < 32; k++) W[k] = W_hh[(g * 32 + lane) * 32 + k];

    float c = 0.f;
    s_h[g][lane] = 0.f;
    __syncthreads();

    const float* preg = g_pre + g * 32 + lane;    // this warp's gate column
    float pc = preg[0 * HC];
    float pn = preg[1 * HC];

    #pragma unroll 1
    for (int n = 0; n < NN; n++) {
        int p = n & 1;
        float pf = preg[(n + 2) * HC];            // prefetch step n+2

        // gate matvec from own h copy: 32 FMAs, 4 split accumulators
        float a0 = pc, a1 = 0.f, a2 = 0.f, a3 = 0.f;
        const float4* h4 = (const float4*)s_h[g];
        #pragma unroll
        for (int q = 0; q < 8; q++) {
            float4 hv = h4[q];
            a0 = fmaf(hv.x, W[4 * q + 0], a0);
            a1 = fmaf(hv.y, W[4 * q + 1], a1);
            a2 = fmaf(hv.z, W[4 * q + 2], a2);
            a3 = fmaf(hv.w, W[4 * q + 3], a3);
        }
        float a = (a0 + a1) + (a2 + a3);

        // per-gate activation (warps 0,1,3 sigmoid; warp 2 tanh)
        float act = (g == 2) ? tnf(a) : sigf(a);
        s_act[p][g][lane] = act;
        __syncthreads();

        // redundant combine (identical in all warps)
        float ia = s_act[p][0][lane];
        float fa = s_act[p][1][lane];
        float ga = s_act[p][2][lane];
        float oa = s_act[p][3][lane];
        c = fmaf(fa, c, ia * ga);
        float hnew = oa * tnf(c);
        if (g == 0) g_hist[n * HID + lane] = hnew;
        s_h[g][lane] = hnew;
        __syncwarp();

        pc = pn; pn = pf;
    }
}

// ---------------- k_out: y = hist @ W_fc + b_fc -----------------------------
__global__ void k_out(const float* __restrict__ W_fc, const float* __restrict__ b_fc,
                      float* __restrict__ out) {
    int gw = (blockIdx.x * blockDim.x + threadIdx.x) >> 5;
    int lane = threadIdx.x & 31;
    if (gw >= NN) return;
    float v = g_hist[gw * HID + lane] * W_fc[lane];
    #pragma unroll
    for (int o = 16; o; o >>= 1) v += __shfl_down_sync(0xffffffffu, v, o);
    if (lane == 0) out[gw] = v + b_fc[0];
}

// ---------------- launch -----------------------------------------------------
extern "C" void kernel_launch(void* const* d_in, const int* in_sizes, int n_in,
                              void* d_out, int out_size) {
    const float* x_seq     = (const float*)d_in[0];
    const int*   edge_index= (const int*  )d_in[1];
    const float* edge_attr = (const float*)d_in[2];
    const float* W_gat     = (const float*)d_in[3];
    const float* att_src   = (const float*)d_in[4];
    const float* att_dst   = (const float*)d_in[5];
    const float* att_edge  = (const float*)d_in[6];
    const float* W_edge    = (const float*)d_in[7];
    const float* gat_bias  = (const float*)d_in[8];
    const float* W_ih      = (const float*)d_in[9];
    const float* W_hh      = (const float*)d_in[10];
    const float* b_ih      = (const float*)d_in[11];
    const float* b_hh      = (const float*)d_in[12];
    const float* W_fc      = (const float*)d_in[13];
    const float* b_fc      = (const float*)d_in[14];
    float* out = (float*)d_out;

    (void)in_sizes; (void)n_in; (void)out_size;

    cudaFuncSetAttribute(k_gatpre, cudaFuncAttributeMaxDynamicSharedMemorySize, HC * HC * 4);

    k_init<<<(NN * HC + 255) / 256, 256>>>(W_edge, att_edge);
    k_easum<<<296, 256>>>(edge_attr);
    k_feat<<<592, 256>>>(x_seq, W_gat, att_src, att_dst);
    int eblocks = (EE + NN + 255) / 256;
    k_pass1<<<eblocks, 256>>>(edge_index, edge_attr);
    k_pass2<<<eblocks, 256>>>(edge_index, edge_attr);
    k_gatpre<<<440, 128, HC * HC * 4>>>(W_ih, b_ih, b_hh, gat_bias);
    k_chain4<<<1, 128>>>(W_hh);
    k_out<<<(NN * 32 + 255) / 256, 256>>>(W_fc, b_fc, out);
}